// round 15
// baseline (speedup 1.0000x reference)
#include <cuda_runtime.h>
#include <math.h>

#define N_NODES    100000
#define N_EDGES    1600000
#define NUM_GRAPHS 4096
#define HID        128
#define F_IN       11
#define F_OUT      19
#define P1         16      // padded input row (floats)
#define P2         24      // padded z row (floats)
#define WCP        20      // padded Wc columns (col 19 = zero)
#define SCAN_B     512
#define SCAN_NB    ((N_NODES + SCAN_B - 1) / SCAN_B)
// tail setup work: pool zero | cnt zero | Wc | bc
#define TAIL_POOL  (NUM_GRAPHS * F_OUT)
#define TAIL_CNT   (TAIL_POOL + NUM_GRAPHS)
#define TAIL_WC    (TAIL_CNT + HID * WCP)
#define TAIL_BC    (TAIL_WC + F_OUT)

#define G2_TILE    128
#define G2_HSTRIDE 132

#define PRE_BLOCKS  296     // 2 blocks/SM x 148 SMs -> guaranteed co-resident
#define PRE_THREADS 512
#define PRE_TOTAL   (PRE_BLOCKS * PRE_THREADS)

// ---------------- static device scratch (zero-initialized at load) ----------------
__device__ float g_xs [(size_t)N_NODES * P1];   // dinv-scaled padded input
__device__ float g_xa [(size_t)N_NODES * P1];   // aggregated input
__device__ float g_z  [(size_t)N_NODES * P2];   // dinv * (h1 @ Wc)
__device__ float g_Wc [HID * WCP];              // W2 @ Wlin (padded)
__device__ float g_bc [F_OUT];                  // b2 @ Wlin + blin
__device__ float g_dinv[N_NODES];
__device__ int   g_ecnt[N_NODES];               // self-cleaned each run
__device__ int   g_rank[N_EDGES];               // rank of edge within its dst bucket
__device__ int   g_rowptr[N_NODES + 1];
__device__ int   g_csr[N_EDGES];
__device__ int   g_blksum[SCAN_NB];
__device__ float g_pool[NUM_GRAPHS * F_OUT];
__device__ int   g_cnt[NUM_GRAPHS];

// ---------------- software grid barrier (persistent kernel, all blocks resident) ----------------
__device__ int               g_bar_cnt;   // self-resets each barrier
__device__ volatile unsigned g_bar_gen;   // monotonically increasing across barriers/replays

__device__ __forceinline__ void gbar(unsigned& gen) {
    __syncthreads();
    if (threadIdx.x == 0) {
        __threadfence();
        unsigned arrived = (unsigned)atomicAdd(&g_bar_cnt, 1);
        if (arrived == PRE_BLOCKS - 1) {
            g_bar_cnt = 0;
            __threadfence();
            g_bar_gen = gen + 1;
        } else {
            while (g_bar_gen == gen) { }
            __threadfence();
        }
    }
    __syncthreads();
    gen++;
}

// ---------------- persistent preprocessing megakernel ----------------
// phase 1: hist (rank) + zero pool/cnt + Wc/bc
// phase 2: scan1 (per-chunk exclusive scan of ecnt)
// phase 3: scan top-level (redundant per block) + finalize rowptr/dinv/xs, ecnt self-clean
// phase 4: atomic-free CSR fill
__global__ void __launch_bounds__(PRE_THREADS, 2)
k_pre(const int* __restrict__ esrc, const int* __restrict__ edst,
      const float* __restrict__ x,
      const float* __restrict__ W2, const float* __restrict__ Wlin,
      const float* __restrict__ b2, const float* __restrict__ blin) {
    int tid = threadIdx.x;
    int gtid = blockIdx.x * PRE_THREADS + tid;
    unsigned gen = g_bar_gen;   // read before first arrive -> race-free

    // ---- phase 1: histogram + setup ----
    for (int e = gtid; e < N_EDGES; e += PRE_TOTAL) {
        int d = __ldg(&edst[e]);
        g_rank[e] = atomicAdd(&g_ecnt[d], 1);
    }
    for (int j = gtid; j < TAIL_BC; j += PRE_TOTAL) {
        if (j < TAIL_POOL) { g_pool[j] = 0.0f; }
        else if (j < TAIL_CNT) { g_cnt[j - TAIL_POOL] = 0; }
        else if (j < TAIL_WC) {
            int i = j - TAIL_CNT;
            int k = i / WCP, f = i % WCP;
            float acc = 0.0f;
            if (f < F_OUT) {
                #pragma unroll 8
                for (int m = 0; m < HID; m++)
                    acc += __ldg(&W2[k * HID + m]) * __ldg(&Wlin[m * F_OUT + f]);
            }
            g_Wc[i] = acc;
        } else {
            int f = j - TAIL_WC;
            float acc = __ldg(&blin[f]);
            #pragma unroll 8
            for (int m = 0; m < HID; m++)
                acc += __ldg(&b2[m]) * __ldg(&Wlin[m * F_OUT + f]);
            g_bc[f] = acc;
        }
    }
    gbar(gen);

    // ---- phase 2: per-chunk exclusive scan (196 virtual blocks of 512) ----
    if (blockIdx.x < SCAN_NB) {
        __shared__ int warp_sums[16];
        int i = blockIdx.x * SCAN_B + tid;
        int v = (i < N_NODES) ? g_ecnt[i] : 0;
        int lane = tid & 31, wid = tid >> 5;
        int incl = v;
        #pragma unroll
        for (int d = 1; d < 32; d <<= 1) {
            int t = __shfl_up_sync(0xffffffffu, incl, d);
            if (lane >= d) incl += t;
        }
        if (lane == 31) warp_sums[wid] = incl;
        __syncthreads();
        if (wid == 0) {
            int s = (lane < 16) ? warp_sums[lane] : 0;
            #pragma unroll
            for (int d = 1; d < 16; d <<= 1) {
                int t = __shfl_up_sync(0xffffffffu, s, d);
                if (lane >= d) s += t;
            }
            if (lane < 16) warp_sums[lane] = s;
        }
        __syncthreads();
        int offset = (wid > 0) ? warp_sums[wid - 1] : 0;
        if (i < N_NODES) g_rowptr[i] = offset + incl - v;
        if (tid == SCAN_B - 1) g_blksum[blockIdx.x] = offset + incl;
    }
    gbar(gen);

    // ---- phase 3: top-level scan (redundant per block) + node finalize ----
    {
        __shared__ int pref[SCAN_NB];
        __shared__ int ws2[16];
        int lane = tid & 31, w = tid >> 5;   // 16 warps
        int v = (tid < SCAN_NB) ? g_blksum[tid] : 0;
        int incl = v;
        #pragma unroll
        for (int d = 1; d < 32; d <<= 1) {
            int u = __shfl_up_sync(0xffffffffu, incl, d);
            if (lane >= d) incl += u;
        }
        if (lane == 31) ws2[w] = incl;
        __syncthreads();
        if (w == 0) {
            int s = (lane < 16) ? ws2[lane] : 0;
            #pragma unroll
            for (int d = 1; d < 16; d <<= 1) {
                int u = __shfl_up_sync(0xffffffffu, s, d);
                if (lane >= d) s += u;
            }
            if (lane < 16) ws2[lane] = s;
        }
        __syncthreads();
        int off = (w > 0) ? ws2[w - 1] : 0;
        if (tid < SCAN_NB) pref[tid] = off + incl - v;
        __syncthreads();

        int i = blockIdx.x * PRE_THREADS + tid;
        if (i < N_NODES) {
            if (i == 0) g_rowptr[N_NODES] = N_EDGES;
            int r = g_rowptr[i] + pref[i / SCAN_B];
            g_rowptr[i] = r;
            int e = g_ecnt[i];
            g_ecnt[i] = 0;                     // self-clean for next replay
            float d = rsqrtf((float)(e + 1));
            g_dinv[i] = d;
            float row[P1];
            #pragma unroll
            for (int f = 0; f < F_IN; f++) row[f] = __ldg(&x[i * F_IN + f]) * d;
            #pragma unroll
            for (int f = F_IN; f < P1; f++) row[f] = 0.0f;
            float4* dst4 = (float4*)(g_xs + (size_t)i * P1);
            dst4[0] = make_float4(row[0], row[1], row[2], row[3]);
            dst4[1] = make_float4(row[4], row[5], row[6], row[7]);
            dst4[2] = make_float4(row[8], row[9], row[10], row[11]);
            dst4[3] = make_float4(row[12], row[13], row[14], row[15]);
        }
    }
    gbar(gen);

    // ---- phase 4: atomic-free CSR fill ----
    for (int e = gtid; e < N_EDGES; e += PRE_TOTAL) {
        int d = __ldg(&edst[e]);
        int p = __ldg(&g_rowptr[d]) + g_rank[e];
        g_csr[p] = __ldg(&esrc[e]);
    }
}

// ---------------- agg1: half-warp per node over 16 padded features (R10 exact) ----------------
__global__ void k_agg1() {
    int half = (blockIdx.x * blockDim.x + threadIdx.x) >> 4;
    int lane = threadIdx.x & 15;
    if (half >= N_NODES) return;
    int node = half;
    float acc = g_xs[(size_t)node * P1 + lane];   // self loop
    int j = g_rowptr[node], end = g_rowptr[node + 1];
    for (; j + 4 <= end; j += 4) {
        int s0 = __ldg(&g_csr[j]);
        int s1 = __ldg(&g_csr[j + 1]);
        int s2 = __ldg(&g_csr[j + 2]);
        int s3 = __ldg(&g_csr[j + 3]);
        acc += g_xs[(size_t)s0 * P1 + lane] + g_xs[(size_t)s1 * P1 + lane]
             + g_xs[(size_t)s2 * P1 + lane] + g_xs[(size_t)s3 * P1 + lane];
    }
    for (; j < end; j++)
        acc += g_xs[(size_t)__ldg(&g_csr[j]) * P1 + lane];
    g_xa[(size_t)node * P1 + lane] = acc;
}

// ---------------- fused GEMM1+GEMM2': tile of 128 nodes (R10 exact) ----------------
__global__ void k_gemm12(const float* __restrict__ W1, const float* __restrict__ b1) {
    extern __shared__ float sh[];
    float* sH  = sh;                          // [128][132]
    float* sWc = sh + G2_TILE * G2_HSTRIDE;   // [128][20]
    int tid = threadIdx.x;                    // 256
    int lane = tid & 31, w = tid >> 5;        // 8 warps
    int base = blockIdx.x * G2_TILE;

    for (int i = tid; i < HID * WCP; i += 256) sWc[i] = g_Wc[i];

    float4 w1r[F_IN];
    #pragma unroll
    for (int k = 0; k < F_IN; k++)
        w1r[k] = __ldg(((const float4*)(W1 + k * HID)) + lane);
    float4 bb = __ldg(((const float4*)b1) + lane);

    #pragma unroll 2
    for (int rep = 0; rep < 16; rep++) {
        int nl = w * 16 + rep;
        int node = base + nl;
        float4 a;
        if (node < N_NODES) {
            float d = g_dinv[node];
            float v = (lane < F_IN) ? g_xa[(size_t)node * P1 + lane] * d : 0.0f;
            a = bb;
            #pragma unroll
            for (int k = 0; k < F_IN; k++) {
                float xk = __shfl_sync(0xffffffffu, v, k);
                a.x += xk * w1r[k].x; a.y += xk * w1r[k].y;
                a.z += xk * w1r[k].z; a.w += xk * w1r[k].w;
            }
            a.x = fmaxf(a.x, 0.f); a.y = fmaxf(a.y, 0.f);
            a.z = fmaxf(a.z, 0.f); a.w = fmaxf(a.w, 0.f);
        } else {
            a = make_float4(0.f, 0.f, 0.f, 0.f);
        }
        *(float4*)(sH + nl * G2_HSTRIDE + lane * 4) = a;
    }
    __syncthreads();

    int fg = tid & 3;
    int nl = tid >> 2;
    float acc0[5] = {0,0,0,0,0}, acc1[5] = {0,0,0,0,0};
    #pragma unroll 4
    for (int k = 0; k < HID; k++) {
        float h0 = sH[nl * G2_HSTRIDE + k];
        float h1 = sH[(nl + 64) * G2_HSTRIDE + k];
        #pragma unroll
        for (int j = 0; j < 5; j++) {
            float wv = sWc[k * WCP + fg * 5 + j];
            acc0[j] += h0 * wv;
            acc1[j] += h1 * wv;
        }
    }
    int n0 = base + nl, n1 = base + nl + 64;
    if (n0 < N_NODES) {
        float d = g_dinv[n0];
        #pragma unroll
        for (int j = 0; j < 5; j++) g_z[(size_t)n0 * P2 + fg * 5 + j] = acc0[j] * d;
    }
    if (n1 < N_NODES) {
        float d = g_dinv[n1];
        #pragma unroll
        for (int j = 0; j < 5; j++) g_z[(size_t)n1 * P2 + fg * 5 + j] = acc1[j] * d;
    }
}

// ---------------- agg2 + fused mean-pool: warp per node, batched prefetch + shfl (R10 exact) ----------------
__global__ void k_agg2(const int* __restrict__ batch) {
    int warp = (blockIdx.x * blockDim.x + threadIdx.x) >> 5;
    int lane = threadIdx.x & 31;
    if (warp >= N_NODES) return;
    int node = warp;
    bool act = lane < WCP;
    float acc = act ? g_z[(size_t)node * P2 + lane] : 0.0f;  // self loop

    int beg = g_rowptr[node], end = g_rowptr[node + 1];
    for (int j = beg; j < end; j += 32) {
        int n = min(32, end - j);
        int s = (lane < n) ? __ldg(&g_csr[j + lane]) : 0;
        int t = 0;
        for (; t + 4 <= n; t += 4) {
            int s0 = __shfl_sync(0xffffffffu, s, t + 0);
            int s1 = __shfl_sync(0xffffffffu, s, t + 1);
            int s2 = __shfl_sync(0xffffffffu, s, t + 2);
            int s3 = __shfl_sync(0xffffffffu, s, t + 3);
            if (act) {
                acc += g_z[(size_t)s0 * P2 + lane] + g_z[(size_t)s1 * P2 + lane]
                     + g_z[(size_t)s2 * P2 + lane] + g_z[(size_t)s3 * P2 + lane];
            }
        }
        for (; t < n; t++) {
            int sv = __shfl_sync(0xffffffffu, s, t);
            if (act) acc += g_z[(size_t)sv * P2 + lane];
        }
    }
    float d = g_dinv[node];
    int g = __ldg(&batch[node]);
    if (lane < F_OUT) atomicAdd(&g_pool[g * F_OUT + lane], acc * d);
    if (lane == 0) atomicAdd(&g_cnt[g], 1);
}

// ---------------- final: out = pool/cnt + bc ----------------
__global__ void k_final(float* __restrict__ out) {
    int idx = blockIdx.x * blockDim.x + threadIdx.x;
    if (idx >= NUM_GRAPHS * F_OUT) return;
    int g = idx / F_OUT, f = idx - g * F_OUT;
    float inv = 1.0f / fmaxf((float)g_cnt[g], 1.0f);
    out[idx] = g_pool[idx] * inv + g_bc[f];
}

// ---------------- launch ----------------
extern "C" void kernel_launch(void* const* d_in, const int* in_sizes, int n_in,
                              void* d_out, int out_size) {
    const float* x    = (const float*)d_in[0];
    const int*   esrc = (const int*)d_in[1];
    const int*   edst = (const int*)d_in[2];
    const int*   batch= (const int*)d_in[3];
    const float* W1   = (const float*)d_in[4];
    const float* b1   = (const float*)d_in[5];
    const float* W2   = (const float*)d_in[6];
    const float* b2   = (const float*)d_in[7];
    const float* Wlin = (const float*)d_in[8];
    const float* blin = (const float*)d_in[9];
    float* out = (float*)d_out;

    const int smem2 = (G2_TILE * G2_HSTRIDE + HID * WCP) * (int)sizeof(float);  // 77.8 KB
    static int attr_set = 0;
    if (!attr_set) {
        cudaFuncSetAttribute(k_gemm12, cudaFuncAttributeMaxDynamicSharedMemorySize, smem2);
        attr_set = 1;
    }

    k_pre   <<<PRE_BLOCKS, PRE_THREADS>>>(esrc, edst, x, W2, Wlin, b2, blin);
    k_agg1  <<<(N_NODES * 16 + 255) / 256, 256>>>();
    k_gemm12<<<(N_NODES + G2_TILE - 1) / G2_TILE, 256, smem2>>>(W1, b1);
    k_agg2  <<<(N_NODES * 32 + 255) / 256, 256>>>(batch);
    k_final <<<(NUM_GRAPHS * F_OUT + 255) / 256, 256>>>(out);
}